// round 3
// baseline (speedup 1.0000x reference)
#include <cuda_runtime.h>
#include <math.h>

// Problem constants (fixed by reference setup)
#define D   512      // d_model
#define NN  512      // sequence length (MAX_SEQ)
#define NQ  16       // NUM_OUT
#define NCH 17       // 16 score channels + 1 v-projection channel
#define BMAX 128

#define SCALE       22.62741699796952f   // sqrt(512)
#define INV_SQRT_DH 0.04419417382415922f // 1/sqrt(512)
#define PE_COEF     (-0.017988946039016837f) // -ln(10000)/512

// ---------------- device scratch (no allocations allowed) ----------------
__device__ float g_qn[NQ * D];        // layernormed queries
__device__ float g_qh[NQ * D];        // q projection
__device__ float g_Kq[NQ * D];        // qh @ Wk
__device__ float g_u[D];              // Wo @ Wv
__device__ float g_G[NCH * D];        // folded per-channel coefficient vectors
__device__ float g_A[NCH];            // sum of G per channel
__device__ float g_C[NCH];            // additive constant per channel
__device__ float g_peT[D * NN];       // transposed reversed positional encoding [d][n]
__device__ float g_scores[BMAX * NQ * NN];
__device__ float g_vproj[BMAX * NN];

// ---------------- f32x2 packed helpers ----------------
__device__ __forceinline__ unsigned long long pk2(float a, float b) {
    unsigned long long r;
    asm("mov.b64 %0, {%1,%2};" : "=l"(r) : "f"(a), "f"(b));
    return r;
}
__device__ __forceinline__ void upk2(unsigned long long v, float& a, float& b) {
    asm("mov.b64 {%0,%1}, %2;" : "=f"(a), "=f"(b) : "l"(v));
}
__device__ __forceinline__ void fma2(unsigned long long& d, unsigned long long a, unsigned long long b) {
    asm("fma.rn.f32x2 %0, %1, %2, %0;" : "+l"(d) : "l"(a), "l"(b));
}
__device__ __forceinline__ void add2(unsigned long long& d, unsigned long long a) {
    asm("add.rn.f32x2 %0, %0, %1;" : "+l"(d) : "l"(a));
}

// ---------------- Kpe: transposed reversed sinusoidal PE table ----------------
__global__ void kpe() {
    int idx = blockIdx.x * blockDim.x + threadIdx.x;   // over D*NN
    int d = idx >> 9;         // NN = 512
    int n = idx & (NN - 1);
    int j = d >> 1;
    float freq = expf(PE_COEF * (float)(2 * j));
    float ang = (float)(NN - 1 - n) * freq;
    g_peT[idx] = (d & 1) ? cosf(ang) : sinf(ang);
}

// ---------------- K0: q = LayerNorm(query * scale) ----------------
__global__ void k0(const float* __restrict__ query,
                   const float* __restrict__ lnqw,
                   const float* __restrict__ lnqb) {
    int tid = threadIdx.x;
    int warp = tid >> 5, lane = tid & 31;
    if (warp < NQ) {
        float xv[16];
        float s = 0.f, s2 = 0.f;
        #pragma unroll
        for (int k = 0; k < 16; k++) {
            int d = lane + 32 * k;
            float v = query[warp * D + d] * SCALE;
            xv[k] = v; s += v; s2 += v * v;
        }
        #pragma unroll
        for (int o = 16; o; o >>= 1) {
            s  += __shfl_xor_sync(0xffffffffu, s,  o);
            s2 += __shfl_xor_sync(0xffffffffu, s2, o);
        }
        float m = s * (1.f / D);
        float var = s2 * (1.f / D) - m * m;
        float inv = rsqrtf(var + 1e-5f);
        #pragma unroll
        for (int k = 0; k < 16; k++) {
            int d = lane + 32 * k;
            g_qn[warp * D + d] = (xv[k] - m) * inv * lnqw[d] + lnqb[d];
        }
    }
}

// ---------------- K1: qh = qn @ Wq.T + bq ----------------
__global__ void k1(const float* __restrict__ Wq, const float* __restrict__ bq) {
    __shared__ float qs[D];
    int q = blockIdx.x;
    int eb = blockIdx.y * 64;
    for (int i = threadIdx.x; i < D; i += blockDim.x) qs[i] = g_qn[q * D + i];
    __syncthreads();
    int warp = threadIdx.x >> 5, lane = threadIdx.x & 31;
    for (int k = 0; k < 8; k++) {
        int e = eb + warp * 8 + k;
        const float* wrow = Wq + (size_t)e * D;
        float s = 0.f;
        #pragma unroll 4
        for (int d = lane; d < D; d += 32) s = fmaf(qs[d], wrow[d], s);
        #pragma unroll
        for (int o = 16; o; o >>= 1) s += __shfl_xor_sync(0xffffffffu, s, o);
        if (lane == 0) g_qh[q * D + e] = s + bq[e];
    }
}

// ---------------- K2: Kq[q][d] = sum_e qh[q][e]*Wk[e][d];  u[d] = sum_e Wo[e]*Wv[e][d]
// grid (17, 4): channel x d-chunk of 128. Deterministic (no atomics).
__global__ void k2(const float* __restrict__ Wk,
                   const float* __restrict__ Wv,
                   const float* __restrict__ Wo) {
    __shared__ float coef[D];
    int ch = blockIdx.x;
    int d = blockIdx.y * 128 + threadIdx.x;
    bool sc = ch < NQ;
    for (int i = threadIdx.x; i < D; i += blockDim.x)
        coef[i] = sc ? g_qh[ch * D + i] : Wo[i];
    __syncthreads();
    const float* W = sc ? Wk : Wv;
    float a = 0.f;
    #pragma unroll 8
    for (int e = 0; e < D; e++)
        a = fmaf(coef[e], W[(size_t)e * D + d], a);
    if (sc) g_Kq[ch * D + d] = a;
    else    g_u[d] = a;
}

// ---------------- K3: fold LN weights; compute G, A, C per channel ----------------
__global__ void k3(const float* __restrict__ lnw, const float* __restrict__ lnb,
                   const float* __restrict__ bk,  const float* __restrict__ bv,
                   const float* __restrict__ Wo) {
    int warp = threadIdx.x >> 5, lane = threadIdx.x & 31;
    if (warp >= NCH) return;
    bool sc = warp < NQ;
    float chS = sc ? INV_SQRT_DH : 1.f;
    float aA = 0.f, aB = 0.f, aC = 0.f;
    for (int d = lane; d < D; d += 32) {
        float src = sc ? g_Kq[warp * D + d] : g_u[d];
        float g = lnw[d] * src * chS;
        g_G[warp * D + d] = g;
        aA += g;
        aB = fmaf(lnb[d], src, aB);
        aC = fmaf(sc ? g_qh[warp * D + d] : bv[d], sc ? bk[d] : Wo[d], aC);
    }
    #pragma unroll
    for (int o = 16; o; o >>= 1) {
        aA += __shfl_xor_sync(0xffffffffu, aA, o);
        aB += __shfl_xor_sync(0xffffffffu, aB, o);
        aC += __shfl_xor_sync(0xffffffffu, aC, o);
    }
    if (lane == 0) {
        g_A[warp] = aA;
        g_C[warp] = (aB + aC) * chS;
    }
}

// ---------------- K4: main streaming pass over latents ----------------
// Each thread handles a packed pair of tokens (n, n+1) via f32x2 math.
// Block = 128 threads = 256 tokens; grid = B*2.
__global__ void __launch_bounds__(128) k4(const float* __restrict__ latents, int B) {
    extern __shared__ unsigned long long Gs2[];  // NCH*D duplicated pairs = 69632 B
    int tid = threadIdx.x;
    for (int i = tid; i < NCH * D; i += 128) {
        float g = g_G[i];
        Gs2[i] = pk2(g, g);
    }
    __syncthreads();

    int b = blockIdx.x >> 1;
    int n2 = ((blockIdx.x & 1) * 128 + tid) * 2;     // even token index
    const float* latB = latents + (size_t)b * D * NN;

    unsigned long long acc[NCH];
    #pragma unroll
    for (int c = 0; c < NCH; c++) acc[c] = 0ull;
    unsigned long long s0 = 0ull, s1 = 0ull;
    const unsigned long long SC2 = pk2(SCALE, SCALE);

    #pragma unroll 4
    for (int d = 0; d < D; d++) {
        unsigned long long lat = *(const unsigned long long*)(latB + (size_t)d * NN + n2);
        unsigned long long x   = *(const unsigned long long*)(g_peT + (size_t)d * NN + n2);
        fma2(x, lat, SC2);           // x = lat*scale + pe
        add2(s0, x);
        fma2(s1, x, x);
        #pragma unroll
        for (int c = 0; c < NCH; c++) fma2(acc[c], x, Gs2[c * D + d]);
    }

    float s0a, s0b, s1a, s1b;
    upk2(s0, s0a, s0b);
    upk2(s1, s1a, s1b);
    float m0 = s0a * (1.f / D), m1 = s0b * (1.f / D);
    float i0 = rsqrtf(s1a * (1.f / D) - m0 * m0 + 1e-5f);
    float i1 = rsqrtf(s1b * (1.f / D) - m1 * m1 + 1e-5f);

    #pragma unroll
    for (int c = 0; c < NQ; c++) {
        float ta, tb; upk2(acc[c], ta, tb);
        float A = g_A[c], Cc = g_C[c];
        float2 o;
        o.x = (ta - m0 * A) * i0 + Cc;
        o.y = (tb - m1 * A) * i1 + Cc;
        *(float2*)(g_scores + ((size_t)b * NQ + c) * NN + n2) = o;
    }
    {
        float ta, tb; upk2(acc[16], ta, tb);
        float A = g_A[16], Cc = g_C[16];
        float2 o;
        o.x = (ta - m0 * A) * i0 + Cc;
        o.y = (tb - m1 * A) * i1 + Cc;
        *(float2*)(g_vproj + (size_t)b * NN + n2) = o;
    }
}

// ---------------- K5: softmax over n + logits + mask handling ----------------
__device__ __forceinline__ float blockReduce(float v, float* red, int isMax) {
    int lane = threadIdx.x & 31, warp = threadIdx.x >> 5;
    #pragma unroll
    for (int o = 16; o; o >>= 1) {
        float t = __shfl_xor_sync(0xffffffffu, v, o);
        v = isMax ? fmaxf(v, t) : v + t;
    }
    if (lane == 0) red[warp] = v;
    __syncthreads();
    if (warp == 0) {
        v = (lane < 8) ? red[lane] : (isMax ? -INFINITY : 0.f);
        #pragma unroll
        for (int o = 4; o; o >>= 1) {
            float t = __shfl_xor_sync(0xffffffffu, v, o);
            v = isMax ? fmaxf(v, t) : v + t;
        }
        if (lane == 0) red[0] = v;
    }
    __syncthreads();
    float r = red[0];
    __syncthreads();
    return r;
}

__global__ void __launch_bounds__(256) k5(const float* __restrict__ qmask,
                                          const float* __restrict__ bo,
                                          float* __restrict__ logits_out,
                                          float* __restrict__ attn_out) {
    __shared__ float red[8];
    int row = blockIdx.x;          // b*16 + q
    int b = row >> 4;
    int tid = threadIdx.x;

    const float* sc = g_scores + (size_t)row * NN;
    float v0 = sc[tid], v1 = sc[tid + 256];

    float mx = blockReduce(fmaxf(v0, v1), red, 1);
    float e0 = expf(v0 - mx), e1 = expf(v1 - mx);

    const float* vp = g_vproj + (size_t)b * NN;
    float S  = blockReduce(e0 + e1, red, 0);
    float Dt = blockReduce(e0 * vp[tid] + e1 * vp[tid + 256], red, 0);

    float qm = qmask[row];
    if (qm != 0.f) {
        float inv = 1.f / S;
        if (attn_out) {
            attn_out[(size_t)row * NN + tid]       = e0 * inv;
            attn_out[(size_t)row * NN + tid + 256] = e1 * inv;
        }
        if (tid == 0 && logits_out) logits_out[row] = Dt * inv + bo[0];
    } else {
        if (attn_out) {
            attn_out[(size_t)row * NN + tid]       = 1.f / NN;
            attn_out[(size_t)row * NN + tid + 256] = 1.f / NN;
        }
        if (tid == 0 && logits_out) logits_out[row] = bo[0];
    }
}

// ---------------- launch ----------------
extern "C" void kernel_launch(void* const* d_in, const int* in_sizes, int n_in,
                              void* d_out, int out_size) {
    const float* latents = (const float*)d_in[0];
    const float* qmask   = (const float*)d_in[1];
    const float* query   = (const float*)d_in[2];
    const float* lnlw    = (const float*)d_in[3];
    const float* lnlb    = (const float*)d_in[4];
    const float* lnqw    = (const float*)d_in[5];
    const float* lnqb    = (const float*)d_in[6];
    const float* Wq      = (const float*)d_in[7];
    const float* bq      = (const float*)d_in[8];
    const float* Wk      = (const float*)d_in[9];
    const float* bk      = (const float*)d_in[10];
    const float* bvv     = (const float*)d_in[12];
    const float* Wv      = (const float*)d_in[11];
    const float* Wo      = (const float*)d_in[13];
    const float* bo      = (const float*)d_in[14];

    int B = in_sizes[0] / (D * NN);
    float* out = (float*)d_out;

    // Output layout: (logits [B,NQ,1], attn_weights [B,1,NQ,NN]) concatenated.
    float* logits_out = nullptr;
    float* attn_out = nullptr;
    if (out_size == B * NQ * (NN + 1)) { logits_out = out; attn_out = out + (size_t)B * NQ; }
    else if (out_size == B * NQ * NN)  { attn_out = out; }
    else                               { logits_out = out; }

    kpe<<<(D * NN) / 256, 256>>>();
    k0<<<1, 512>>>(query, lnqw, lnqb);
    k1<<<dim3(16, 8), 256>>>(Wq, bq);
    k2<<<dim3(NCH, 4), 128>>>(Wk, Wv, Wo);
    k3<<<1, NCH * 32>>>(lnlw, lnlb, bk, bvv, Wo);

    cudaFuncSetAttribute(k4, cudaFuncAttributeMaxDynamicSharedMemorySize, NCH * D * 8);
    k4<<<B * 2, 128, NCH * D * 8>>>(latents, B);

    k5<<<B * NQ, 256>>>(qmask, bo, logits_out, attn_out);
}

// round 4
// speedup vs baseline: 1.3832x; 1.3832x over previous
#include <cuda_runtime.h>
#include <math.h>

#define D   512
#define NN  512
#define NQ  16
#define NCH 17
#define BMAX 128
#define NECH 16   // e-chunks in k2p (32 e each)

#define SCALE       22.62741699796952f
#define INV_SQRT_DH 0.04419417382415922f
#define PE_COEF     (-0.017988946039016837f)

typedef unsigned long long ull;

// ---------------- device scratch ----------------
__device__ float g_qh[NQ * D];
__device__ float g_part[NECH * NCH * D];
__device__ float g_G[NCH * D];
__device__ float g_A[NCH];
__device__ float g_C[NCH];
__device__ __align__(16) float g_peT[D * NN];
__device__ __align__(16) float g_scores[BMAX * NQ * NN];
__device__ __align__(16) float g_vproj[BMAX * NN];

// ---------------- f32x2 helpers ----------------
__device__ __forceinline__ ull pk2(float a, float b) {
    ull r; asm("mov.b64 %0, {%1,%2};" : "=l"(r) : "f"(a), "f"(b)); return r;
}
__device__ __forceinline__ void upk2(ull v, float& a, float& b) {
    asm("mov.b64 {%0,%1}, %2;" : "=f"(a), "=f"(b) : "l"(v));
}
__device__ __forceinline__ void fma2(ull& d, ull a, ull b) {
    asm("fma.rn.f32x2 %0, %1, %2, %0;" : "+l"(d) : "l"(a), "l"(b));
}
__device__ __forceinline__ void add2(ull& d, ull a) {
    asm("add.rn.f32x2 %0, %0, %1;" : "+l"(d) : "l"(a));
}

// ---------------- Kpe: transposed reversed sinusoidal PE [d][n] ----------------
__global__ void kpe() {
    int idx = blockIdx.x * blockDim.x + threadIdx.x;
    int d = idx >> 9;
    int n = idx & (NN - 1);
    int j = d >> 1;
    float freq = expf(PE_COEF * (float)(2 * j));
    float ang = (float)(NN - 1 - n) * freq;
    g_peT[idx] = (d & 1) ? cosf(ang) : sinf(ang);
}

// ---------------- K01: q-LN fused with Wq projection ----------------
// grid (16 q, 8 e-chunks of 64), 256 threads. Each block recomputes the (tiny) LN.
__global__ void k01(const float* __restrict__ query,
                    const float* __restrict__ lnqw,
                    const float* __restrict__ lnqb,
                    const float* __restrict__ Wq,
                    const float* __restrict__ bq) {
    __shared__ float qs[D];
    __shared__ float r1[8], r2[8];
    int q = blockIdx.x, eb = blockIdx.y * 64;
    int tid = threadIdx.x, warp = tid >> 5, lane = tid & 31;

    float v0 = query[q * D + tid] * SCALE;
    float v1 = query[q * D + tid + 256] * SCALE;
    float s = v0 + v1, s2 = v0 * v0 + v1 * v1;
    #pragma unroll
    for (int o = 16; o; o >>= 1) {
        s  += __shfl_xor_sync(0xffffffffu, s,  o);
        s2 += __shfl_xor_sync(0xffffffffu, s2, o);
    }
    if (lane == 0) { r1[warp] = s; r2[warp] = s2; }
    __syncthreads();
    if (tid == 0) {
        float a = 0.f, b = 0.f;
        #pragma unroll
        for (int w = 0; w < 8; w++) { a += r1[w]; b += r2[w]; }
        r1[0] = a; r2[0] = b;
    }
    __syncthreads();
    float m = r1[0] * (1.f / D);
    float inv = rsqrtf(r2[0] * (1.f / D) - m * m + 1e-5f);
    qs[tid]       = (v0 - m) * inv * lnqw[tid] + lnqb[tid];
    qs[tid + 256] = (v1 - m) * inv * lnqw[tid + 256] + lnqb[tid + 256];
    __syncthreads();

    #pragma unroll
    for (int k = 0; k < 8; k++) {
        int e = eb + warp * 8 + k;
        const float* wrow = Wq + (size_t)e * D;
        float acc = 0.f;
        #pragma unroll 4
        for (int d = lane; d < D; d += 32) acc = fmaf(qs[d], wrow[d], acc);
        #pragma unroll
        for (int o = 16; o; o >>= 1) acc += __shfl_xor_sync(0xffffffffu, acc, o);
        if (lane == 0) g_qh[q * D + e] = acc + bq[e];
    }
}

// ---------------- K2p: split-E partials for Kq (16 ch) and u (ch 16) ----------------
// grid (4 d-chunks of 128, 16 e-chunks of 32), 128 threads.
// Each block reads Wk/Wv chunk ONCE and accumulates all 17 channels.
__global__ void __launch_bounds__(128) k2p(const float* __restrict__ Wk,
                                           const float* __restrict__ Wv,
                                           const float* __restrict__ Wo) {
    __shared__ float cf[NCH * 32];
    int d = blockIdx.x * 128 + threadIdx.x;
    int ech = blockIdx.y;
    for (int i = threadIdx.x; i < NCH * 32; i += 128) {
        int ch = i >> 5, e = ech * 32 + (i & 31);
        cf[i] = (ch < NQ) ? g_qh[ch * D + e] : Wo[e];
    }
    __syncthreads();

    float acc[NCH];
    #pragma unroll
    for (int c = 0; c < NCH; c++) acc[c] = 0.f;
    #pragma unroll 4
    for (int ee = 0; ee < 32; ee++) {
        int e = ech * 32 + ee;
        float wk = Wk[(size_t)e * D + d];
        float wv = Wv[(size_t)e * D + d];
        #pragma unroll
        for (int c = 0; c < NQ; c++) acc[c] = fmaf(cf[c * 32 + ee], wk, acc[c]);
        acc[16] = fmaf(cf[16 * 32 + ee], wv, acc[16]);
    }
    #pragma unroll
    for (int c = 0; c < NCH; c++)
        g_part[((size_t)ech * NCH + c) * D + d] = acc[c];
}

// ---------------- K3r: reduce partials + fold LN weights -> G, A, C ----------------
// grid 17 (channels), 512 threads (d).
__global__ void k3r(const float* __restrict__ lnw, const float* __restrict__ lnb,
                    const float* __restrict__ bk,  const float* __restrict__ bv,
                    const float* __restrict__ Wo) {
    __shared__ float rA[16], rB[16], rC[16];
    int ch = blockIdx.x;
    int d = threadIdx.x, warp = d >> 5, lane = d & 31;
    bool sc = ch < NQ;
    float chS = sc ? INV_SQRT_DH : 1.f;

    float src = 0.f;
    #pragma unroll
    for (int p = 0; p < NECH; p++)
        src += g_part[((size_t)p * NCH + ch) * D + d];

    float g = lnw[d] * src * chS;
    g_G[ch * D + d] = g;
    float aA = g;
    float aB = lnb[d] * src;
    float aC = sc ? g_qh[ch * D + d] * bk[d] : bv[d] * Wo[d];

    #pragma unroll
    for (int o = 16; o; o >>= 1) {
        aA += __shfl_xor_sync(0xffffffffu, aA, o);
        aB += __shfl_xor_sync(0xffffffffu, aB, o);
        aC += __shfl_xor_sync(0xffffffffu, aC, o);
    }
    if (lane == 0) { rA[warp] = aA; rB[warp] = aB; rC[warp] = aC; }
    __syncthreads();
    if (threadIdx.x == 0) {
        float A = 0.f, Bv = 0.f, C = 0.f;
        #pragma unroll
        for (int w = 0; w < 16; w++) { A += rA[w]; Bv += rB[w]; C += rC[w]; }
        g_A[ch] = A;
        g_C[ch] = (Bv + C) * chS;
    }
}

// ---------------- K4: main streaming pass ----------------
// grid B, block 128. Each thread: 4 tokens (2 f32x2 pairs). d processed in
// steps of 2 so each G coefficient fetch is one LDS.128 feeding 4 FFMA2.
__global__ void __launch_bounds__(128) k4(const float* __restrict__ latents) {
    extern __shared__ ull Gs2[];   // NCH*D duplicated pairs (69632 B)
    int tid = threadIdx.x;
    for (int i = tid; i < NCH * D; i += 128) {
        float g = g_G[i];
        Gs2[i] = pk2(g, g);
    }
    __syncthreads();

    int b = blockIdx.x;
    int n4 = tid * 4;
    const float* latB = latents + (size_t)b * D * NN;

    ull accA[NCH], accB[NCH];
    #pragma unroll
    for (int c = 0; c < NCH; c++) { accA[c] = 0ull; accB[c] = 0ull; }
    ull s0a = 0ull, s1a = 0ull, s0b = 0ull, s1b = 0ull;
    const ull SC2 = pk2(SCALE, SCALE);

    #pragma unroll 4
    for (int d = 0; d < D; d += 2) {
        ulonglong2 lat0 = *(const ulonglong2*)(latB + (size_t)d * NN + n4);
        ulonglong2 pe0  = *(const ulonglong2*)(g_peT + (size_t)d * NN + n4);
        ulonglong2 lat1 = *(const ulonglong2*)(latB + (size_t)(d + 1) * NN + n4);
        ulonglong2 pe1  = *(const ulonglong2*)(g_peT + (size_t)(d + 1) * NN + n4);

        ull x00 = pe0.x; fma2(x00, lat0.x, SC2);   // tokens n4,n4+1 @ d
        ull x01 = pe0.y; fma2(x01, lat0.y, SC2);   // tokens n4+2,n4+3 @ d
        ull x10 = pe1.x; fma2(x10, lat1.x, SC2);   // @ d+1
        ull x11 = pe1.y; fma2(x11, lat1.y, SC2);

        add2(s0a, x00); fma2(s1a, x00, x00);
        add2(s0b, x01); fma2(s1b, x01, x01);
        add2(s0a, x10); fma2(s1a, x10, x10);
        add2(s0b, x11); fma2(s1b, x11, x11);

        #pragma unroll
        for (int c = 0; c < NCH; c++) {
            ulonglong2 g2 = *(const ulonglong2*)&Gs2[c * D + d];  // {g_d,g_d},{g_d+1,g_d+1}
            fma2(accA[c], x00, g2.x);
            fma2(accB[c], x01, g2.x);
            fma2(accA[c], x10, g2.y);
            fma2(accB[c], x11, g2.y);
        }
    }

    float s0t[4], s1t[4];
    upk2(s0a, s0t[0], s0t[1]); upk2(s0b, s0t[2], s0t[3]);
    upk2(s1a, s1t[0], s1t[1]); upk2(s1b, s1t[2], s1t[3]);
    float m[4], iv[4];
    #pragma unroll
    for (int t = 0; t < 4; t++) {
        m[t]  = s0t[t] * (1.f / D);
        iv[t] = rsqrtf(s1t[t] * (1.f / D) - m[t] * m[t] + 1e-5f);
    }

    #pragma unroll
    for (int c = 0; c < NCH; c++) {
        float A = g_A[c], Cc = g_C[c];
        float t0, t1, t2, t3;
        upk2(accA[c], t0, t1);
        upk2(accB[c], t2, t3);
        float4 o;
        o.x = (t0 - m[0] * A) * iv[0] + Cc;
        o.y = (t1 - m[1] * A) * iv[1] + Cc;
        o.z = (t2 - m[2] * A) * iv[2] + Cc;
        o.w = (t3 - m[3] * A) * iv[3] + Cc;
        if (c < NQ)
            *(float4*)(g_scores + ((size_t)b * NQ + c) * NN + n4) = o;
        else
            *(float4*)(g_vproj + (size_t)b * NN + n4) = o;
    }
}

// ---------------- K5: softmax + logits ----------------
__device__ __forceinline__ float blockReduce(float v, float* red, int isMax) {
    int lane = threadIdx.x & 31, warp = threadIdx.x >> 5;
    #pragma unroll
    for (int o = 16; o; o >>= 1) {
        float t = __shfl_xor_sync(0xffffffffu, v, o);
        v = isMax ? fmaxf(v, t) : v + t;
    }
    if (lane == 0) red[warp] = v;
    __syncthreads();
    if (warp == 0) {
        v = (lane < 8) ? red[lane] : (isMax ? -INFINITY : 0.f);
        #pragma unroll
        for (int o = 4; o; o >>= 1) {
            float t = __shfl_xor_sync(0xffffffffu, v, o);
            v = isMax ? fmaxf(v, t) : v + t;
        }
        if (lane == 0) red[0] = v;
    }
    __syncthreads();
    float r = red[0];
    __syncthreads();
    return r;
}

__global__ void __launch_bounds__(256) k5(const float* __restrict__ qmask,
                                          const float* __restrict__ bo,
                                          float* __restrict__ logits_out,
                                          float* __restrict__ attn_out) {
    __shared__ float red[8];
    int row = blockIdx.x;          // b*16 + q
    int b = row >> 4;
    int tid = threadIdx.x;

    const float* sc = g_scores + (size_t)row * NN;
    float v0 = sc[tid], v1 = sc[tid + 256];

    float mx = blockReduce(fmaxf(v0, v1), red, 1);
    float e0 = expf(v0 - mx), e1 = expf(v1 - mx);

    const float* vp = g_vproj + (size_t)b * NN;
    float S  = blockReduce(e0 + e1, red, 0);
    float Dt = blockReduce(e0 * vp[tid] + e1 * vp[tid + 256], red, 0);

    float qm = qmask[row];
    if (qm != 0.f) {
        float inv = 1.f / S;
        if (attn_out) {
            attn_out[(size_t)row * NN + tid]       = e0 * inv;
            attn_out[(size_t)row * NN + tid + 256] = e1 * inv;
        }
        if (tid == 0 && logits_out) logits_out[row] = Dt * inv + bo[0];
    } else {
        if (attn_out) {
            attn_out[(size_t)row * NN + tid]       = 1.f / NN;
            attn_out[(size_t)row * NN + tid + 256] = 1.f / NN;
        }
        if (tid == 0 && logits_out) logits_out[row] = bo[0];
    }
}

// ---------------- launch ----------------
extern "C" void kernel_launch(void* const* d_in, const int* in_sizes, int n_in,
                              void* d_out, int out_size) {
    const float* latents = (const float*)d_in[0];
    const float* qmask   = (const float*)d_in[1];
    const float* query   = (const float*)d_in[2];
    const float* lnlw    = (const float*)d_in[3];
    const float* lnlb    = (const float*)d_in[4];
    const float* lnqw    = (const float*)d_in[5];
    const float* lnqb    = (const float*)d_in[6];
    const float* Wq      = (const float*)d_in[7];
    const float* bq      = (const float*)d_in[8];
    const float* Wk      = (const float*)d_in[9];
    const float* bk      = (const float*)d_in[10];
    const float* Wv      = (const float*)d_in[11];
    const float* bvv     = (const float*)d_in[12];
    const float* Wo      = (const float*)d_in[13];
    const float* bo      = (const float*)d_in[14];

    int B = in_sizes[0] / (D * NN);
    float* out = (float*)d_out;

    float* logits_out = nullptr;
    float* attn_out = nullptr;
    if (out_size == B * NQ * (NN + 1)) { logits_out = out; attn_out = out + (size_t)B * NQ; }
    else if (out_size == B * NQ * NN)  { attn_out = out; }
    else                               { logits_out = out; }

    kpe<<<(D * NN) / 256, 256>>>();
    k01<<<dim3(16, 8), 256>>>(query, lnqw, lnqb, Wq, bq);
    k2p<<<dim3(4, NECH), 128>>>(Wk, Wv, Wo);
    k3r<<<NCH, 512>>>(lnlw, lnlb, bk, bvv, Wo);

    cudaFuncSetAttribute(k4, cudaFuncAttributeMaxDynamicSharedMemorySize, NCH * D * 8);
    k4<<<B, 128, NCH * D * 8>>>(latents);

    k5<<<B * NQ, 256>>>(qmask, bo, logits_out, attn_out);
}

// round 7
// speedup vs baseline: 2.1216x; 1.5339x over previous
#include <cuda_runtime.h>
#include <math.h>

#define D   512
#define NN  512
#define NQ  16
#define NCH 17
#define NECH 16

#define SCALE       22.62741699796952f
#define INV_SQRT_DH 0.04419417382415922f
#define PE_COEF     (-0.017988946039016837f)

typedef unsigned long long ull;

// ---------------- device scratch ----------------
__device__ float g_qh[NQ * D];
__device__ float g_part[NECH * NCH * D];
__device__ float g_G[NCH * D];
__device__ float g_A[NCH];
__device__ float g_C[NCH];
__device__ __align__(16) float g_peT[D * NN];

// ---------------- f32x2 helpers ----------------
__device__ __forceinline__ ull pk2(float a, float b) {
    ull r; asm("mov.b64 %0, {%1,%2};" : "=l"(r) : "f"(a), "f"(b)); return r;
}
__device__ __forceinline__ void upk2(ull v, float& a, float& b) {
    asm("mov.b64 {%0,%1}, %2;" : "=f"(a), "=f"(b) : "l"(v));
}
__device__ __forceinline__ void fma2(ull& d, ull a, ull b) {
    asm("fma.rn.f32x2 %0, %1, %2, %0;" : "+l"(d) : "l"(a), "l"(b));
}
__device__ __forceinline__ void add2(ull& d, ull a) {
    asm("add.rn.f32x2 %0, %0, %1;" : "+l"(d) : "l"(a));
}

// ---------------- kprep: PE table (blocks 0..1023) + q-LN@Wq (blocks 1024..1151) ----------------
__global__ void kprep(const float* __restrict__ query,
                      const float* __restrict__ lnqw,
                      const float* __restrict__ lnqb,
                      const float* __restrict__ Wq,
                      const float* __restrict__ bq) {
    if (blockIdx.x < 1024) {
        int idx = blockIdx.x * 256 + threadIdx.x;
        int d = idx >> 9;
        int n = idx & (NN - 1);
        int j = d >> 1;
        float freq = expf(PE_COEF * (float)(2 * j));
        float ang = (float)(NN - 1 - n) * freq;
        g_peT[idx] = (d & 1) ? cosf(ang) : sinf(ang);
        return;
    }
    __shared__ float qs[D];
    __shared__ float r1[8], r2[8];
    int bb = blockIdx.x - 1024;
    int q = bb >> 3, eb = (bb & 7) * 64;
    int tid = threadIdx.x, warp = tid >> 5, lane = tid & 31;

    float v0 = query[q * D + tid] * SCALE;
    float v1 = query[q * D + tid + 256] * SCALE;
    float s = v0 + v1, s2 = v0 * v0 + v1 * v1;
    #pragma unroll
    for (int o = 16; o; o >>= 1) {
        s  += __shfl_xor_sync(0xffffffffu, s,  o);
        s2 += __shfl_xor_sync(0xffffffffu, s2, o);
    }
    if (lane == 0) { r1[warp] = s; r2[warp] = s2; }
    __syncthreads();
    if (tid == 0) {
        float a = 0.f, b = 0.f;
        #pragma unroll
        for (int w = 0; w < 8; w++) { a += r1[w]; b += r2[w]; }
        r1[0] = a; r2[0] = b;
    }
    __syncthreads();
    float m = r1[0] * (1.f / D);
    float inv = rsqrtf(r2[0] * (1.f / D) - m * m + 1e-5f);
    qs[tid]       = (v0 - m) * inv * lnqw[tid] + lnqb[tid];
    qs[tid + 256] = (v1 - m) * inv * lnqw[tid + 256] + lnqb[tid + 256];
    __syncthreads();

    #pragma unroll
    for (int k = 0; k < 8; k++) {
        int e = eb + warp * 8 + k;
        const float* wrow = Wq + (size_t)e * D;
        float acc = 0.f;
        #pragma unroll 4
        for (int d = lane; d < D; d += 32) acc = fmaf(qs[d], wrow[d], acc);
        #pragma unroll
        for (int o = 16; o; o >>= 1) acc += __shfl_xor_sync(0xffffffffu, acc, o);
        if (lane == 0) g_qh[q * D + e] = acc + bq[e];
    }
}

// ---------------- k2p: split-E partials for Kq (16 ch) and u (ch 16) ----------------
__global__ void __launch_bounds__(128) k2p(const float* __restrict__ Wk,
                                           const float* __restrict__ Wv,
                                           const float* __restrict__ Wo) {
    __shared__ float cf[NCH * 32];
    int d = blockIdx.x * 128 + threadIdx.x;
    int ech = blockIdx.y;
    for (int i = threadIdx.x; i < NCH * 32; i += 128) {
        int ch = i >> 5, e = ech * 32 + (i & 31);
        cf[i] = (ch < NQ) ? g_qh[ch * D + e] : Wo[e];
    }
    __syncthreads();

    float acc[NCH];
    #pragma unroll
    for (int c = 0; c < NCH; c++) acc[c] = 0.f;
    #pragma unroll 4
    for (int ee = 0; ee < 32; ee++) {
        int e = ech * 32 + ee;
        float wk = Wk[(size_t)e * D + d];
        float wv = Wv[(size_t)e * D + d];
        #pragma unroll
        for (int c = 0; c < NQ; c++) acc[c] = fmaf(cf[c * 32 + ee], wk, acc[c]);
        acc[16] = fmaf(cf[16 * 32 + ee], wv, acc[16]);
    }
    #pragma unroll
    for (int c = 0; c < NCH; c++)
        g_part[((size_t)ech * NCH + c) * D + d] = acc[c];
}

// ---------------- k3r: reduce partials + fold LN weights -> G, A, C ----------------
__global__ void k3r(const float* __restrict__ lnw, const float* __restrict__ lnb,
                    const float* __restrict__ bk,  const float* __restrict__ bv,
                    const float* __restrict__ Wo) {
    __shared__ float rA[16], rB[16], rC[16];
    int ch = blockIdx.x;
    int d = threadIdx.x, warp = d >> 5, lane = d & 31;
    bool sc = ch < NQ;
    float chS = sc ? INV_SQRT_DH : 1.f;

    float src = 0.f;
    #pragma unroll
    for (int p = 0; p < NECH; p++)
        src += g_part[((size_t)p * NCH + ch) * D + d];

    float g = lnw[d] * src * chS;
    g_G[ch * D + d] = g;
    float aA = g;
    float aB = lnb[d] * src;
    float aC = sc ? g_qh[ch * D + d] * bk[d] : bv[d] * Wo[d];

    #pragma unroll
    for (int o = 16; o; o >>= 1) {
        aA += __shfl_xor_sync(0xffffffffu, aA, o);
        aB += __shfl_xor_sync(0xffffffffu, aB, o);
        aC += __shfl_xor_sync(0xffffffffu, aC, o);
    }
    if (lane == 0) { rA[warp] = aA; rB[warp] = aB; rC[warp] = aC; }
    __syncthreads();
    if (threadIdx.x == 0) {
        float A = 0.f, Bv = 0.f, C = 0.f;
        #pragma unroll
        for (int w = 0; w < 16; w++) { A += rA[w]; Bv += rB[w]; C += rC[w]; }
        g_A[ch] = A;
        g_C[ch] = (Bv + C) * chS;
    }
}

// ---------------- k4f: fused streaming + softmax + logits ----------------
// grid B, 256 threads, 2 tokens/thread (one f32x2 pair). Whole batch row in
// one block -> softmax fused, scores never touch DRAM.
__global__ void __launch_bounds__(256, 1) k4f(const float* __restrict__ latents,
                                              const float* __restrict__ qmask,
                                              const float* __restrict__ bo,
                                              float* __restrict__ logits_out,
                                              float* __restrict__ attn_out) {
    extern __shared__ ull Gs2[];   // NCH*D duplicated pairs (69632 B)
    __shared__ float redA[8], redB[8], redC[8];
    int tid = threadIdx.x;
    for (int i = tid; i < NCH * D; i += 256) {
        float g = g_G[i];
        Gs2[i] = pk2(g, g);
    }
    __syncthreads();

    int b = blockIdx.x;
    int n2 = tid * 2;
    const float* latB = latents + (size_t)b * D * NN;

    ull acc[NCH];
    #pragma unroll
    for (int c = 0; c < NCH; c++) acc[c] = 0ull;
    ull s0 = 0ull, s1 = 0ull;
    const ull SC2 = pk2(SCALE, SCALE);

    #pragma unroll 4
    for (int d = 0; d < D; d += 2) {
        ull lat0 = *(const ull*)(latB + (size_t)d * NN + n2);
        ull lat1 = *(const ull*)(latB + (size_t)(d + 1) * NN + n2);
        ull x0   = *(const ull*)(g_peT + (size_t)d * NN + n2);
        ull x1   = *(const ull*)(g_peT + (size_t)(d + 1) * NN + n2);
        fma2(x0, lat0, SC2);
        fma2(x1, lat1, SC2);
        add2(s0, x0); fma2(s1, x0, x0);
        add2(s0, x1); fma2(s1, x1, x1);
        #pragma unroll
        for (int c = 0; c < NCH; c++) {
            ulonglong2 g2 = *(const ulonglong2*)&Gs2[c * D + d];
            fma2(acc[c], x0, g2.x);
            fma2(acc[c], x1, g2.y);
        }
    }

    float sA, sB, qA, qB;
    upk2(s0, sA, sB);
    upk2(s1, qA, qB);
    float m0 = sA * (1.f / D), m1 = sB * (1.f / D);
    float i0 = rsqrtf(qA * (1.f / D) - m0 * m0 + 1e-5f);
    float i1 = rsqrtf(qB * (1.f / D) - m1 * m1 + 1e-5f);

    float sc0[NCH], sc1[NCH];
    #pragma unroll
    for (int c = 0; c < NCH; c++) {
        float t0, t1; upk2(acc[c], t0, t1);
        float A = g_A[c], Cc = g_C[c];
        sc0[c] = (t0 - m0 * A) * i0 + Cc;
        sc1[c] = (t1 - m1 * A) * i1 + Cc;
    }
    float v0 = sc0[16], v1 = sc1[16];

    int lane = tid & 31, warp = tid >> 5;
    float bo0 = bo[0];

    #pragma unroll 1
    for (int c = 0; c < NQ; c++) {
        // block max
        float mx = fmaxf(sc0[c], sc1[c]);
        #pragma unroll
        for (int o = 16; o; o >>= 1) mx = fmaxf(mx, __shfl_xor_sync(0xffffffffu, mx, o));
        if (lane == 0) redA[warp] = mx;
        __syncthreads();
        mx = redA[0];
        #pragma unroll
        for (int w = 1; w < 8; w++) mx = fmaxf(mx, redA[w]);

        float e0 = expf(sc0[c] - mx);
        float e1 = expf(sc1[c] - mx);
        float ps = e0 + e1;
        float pd = e0 * v0 + e1 * v1;
        #pragma unroll
        for (int o = 16; o; o >>= 1) {
            ps += __shfl_xor_sync(0xffffffffu, ps, o);
            pd += __shfl_xor_sync(0xffffffffu, pd, o);
        }
        if (lane == 0) { redB[warp] = ps; redC[warp] = pd; }
        __syncthreads();
        float S = redB[0], Dt = redC[0];
        #pragma unroll
        for (int w = 1; w < 8; w++) { S += redB[w]; Dt += redC[w]; }

        int row = b * NQ + c;
        float qm = qmask[row];
        if (qm != 0.f) {
            float inv = 1.f / S;
            if (attn_out) {
                float2 o2; o2.x = e0 * inv; o2.y = e1 * inv;
                *(float2*)(attn_out + (size_t)row * NN + n2) = o2;
            }
            if (tid == 0 && logits_out) logits_out[row] = Dt * inv + bo0;
        } else {
            if (attn_out) {
                float2 o2; o2.x = 1.f / NN; o2.y = 1.f / NN;
                *(float2*)(attn_out + (size_t)row * NN + n2) = o2;
            }
            if (tid == 0 && logits_out) logits_out[row] = bo0;
        }
        __syncthreads();   // protect redA/redB/redC reuse next channel
    }
}

// ---------------- launch ----------------
extern "C" void kernel_launch(void* const* d_in, const int* in_sizes, int n_in,
                              void* d_out, int out_size) {
    const float* latents = (const float*)d_in[0];
    const float* qmask   = (const float*)d_in[1];
    const float* query   = (const float*)d_in[2];
    const float* lnlw    = (const float*)d_in[3];
    const float* lnlb    = (const float*)d_in[4];
    const float* lnqw    = (const float*)d_in[5];
    const float* lnqb    = (const float*)d_in[6];
    const float* Wq      = (const float*)d_in[7];
    const float* bq      = (const float*)d_in[8];
    const float* Wk      = (const float*)d_in[9];
    const float* bk      = (const float*)d_in[10];
    const float* Wv      = (const float*)d_in[11];
    const float* bvv     = (const float*)d_in[12];
    const float* Wo      = (const float*)d_in[13];
    const float* bo      = (const float*)d_in[14];

    int B = in_sizes[0] / (D * NN);
    float* out = (float*)d_out;

    float* logits_out = nullptr;
    float* attn_out = nullptr;
    if (out_size == B * NQ * (NN + 1)) { logits_out = out; attn_out = out + (size_t)B * NQ; }
    else if (out_size == B * NQ * NN)  { attn_out = out; }
    else                               { logits_out = out; }

    kprep<<<1024 + 128, 256>>>(query, lnqw, lnqb, Wq, bq);
    k2p<<<dim3(4, NECH), 128>>>(Wk, Wv, Wo);
    k3r<<<NCH, 512>>>(lnlw, lnlb, bk, bvv, Wo);

    cudaFuncSetAttribute(k4f, cudaFuncAttributeMaxDynamicSharedMemorySize, NCH * D * 8);
    k4f<<<B, 256, NCH * D * 8>>>(latents, qmask, bo, logits_out, attn_out);
}